// round 15
// baseline (speedup 1.0000x reference)
#include <cuda_runtime.h>
#include <cuda_fp16.h>
#include <math.h>
#include <stdint.h>

#define B_   2
#define S_   2048
#define T_   4096      // B*S tokens
#define DIM_ 1024
#define SCALE_ 0.08838834764831845f   // 1/sqrt(128)
#define KP   200       // padded pitch for qe/keff (gmem AND smem)

// ---------------- scratch (static device arrays) -----------------------------
__device__ __half g_xcat[T_ * 3072];       // [x_hi | x_lo | x_hi]
__device__ __half g_wdqkv[3072 * 384];     // stacked [Wdq|Wdkv] hi/hi/lo
__device__ float  g_bias_dqkv[384];
__device__ float  g_dqkv[2 * T_ * 384];    // split-K partials (contiguous)
__device__ __half g_cqcat[T_ * 384];       // [cq_hi | cq_lo | cq_hi]
__device__ __half g_wuqeff[384 * 1536];    // absorbed uq weights hi/hi/lo (scaled)
__device__ float  g_biaseff[1536];
__device__ __half g_qe[16 * S_ * KP];      // q_eff [bh][s][KP] fp16 (cols 0..191 valid)
__device__ __half g_keff[T_ * KP];         // [ckv_norm(128) | roped krope(64) | pad]
__device__ __half g_attnlat[T_ * 1024];    // attn latent [t][h*128+c] fp16
__device__ __half g_wfA[8 * 128 * 768];
__device__ __half g_wfB[8 * 768 * 1024];
__device__ __half g_wfused[1024 * 1024];
__device__ float  g_bopart[16 * 1024];
__device__ float  g_boeff[1024];
__device__ float  g_zb[1536];

// ---------------- helpers ------------------------------------------------------
__device__ __forceinline__ uint32_t smem_u32(const void* p) {
    return (uint32_t)__cvta_generic_to_shared(p);
}
__device__ __forceinline__ void ldsm_x4(uint32_t* r, uint32_t addr) {
    asm volatile("ldmatrix.sync.aligned.m8n8.x4.shared.b16 {%0,%1,%2,%3},[%4];"
                 : "=r"(r[0]), "=r"(r[1]), "=r"(r[2]), "=r"(r[3]) : "r"(addr));
}
__device__ __forceinline__ void ldsm_x4_t(uint32_t* r, uint32_t addr) {
    asm volatile("ldmatrix.sync.aligned.m8n8.x4.trans.shared.b16 {%0,%1,%2,%3},[%4];"
                 : "=r"(r[0]), "=r"(r[1]), "=r"(r[2]), "=r"(r[3]) : "r"(addr));
}
__device__ __forceinline__ void mma16816(float* c, const uint32_t* a, const uint32_t* b) {
    asm volatile(
        "mma.sync.aligned.m16n8k16.row.col.f32.f16.f16.f32 "
        "{%0,%1,%2,%3},{%4,%5,%6,%7},{%8,%9},{%0,%1,%2,%3};"
        : "+f"(c[0]), "+f"(c[1]), "+f"(c[2]), "+f"(c[3])
        : "r"(a[0]), "r"(a[1]), "r"(a[2]), "r"(a[3]), "r"(b[0]), "r"(b[1]));
}
__device__ __forceinline__ uint32_t pack_h2(float lo, float hi) {
    __half2 h = __floats2half2_rn(lo, hi);
    return *(uint32_t*)&h;
}
__device__ __forceinline__ void cp16(void* smem_dst, const void* gsrc) {
    asm volatile("cp.async.cg.shared.global [%0],[%1],16;"
                 :: "r"(smem_u32(smem_dst)), "l"(gsrc));
}
#define CP_COMMIT() asm volatile("cp.async.commit_group;")
#define CP_WAIT(n)  asm volatile("cp.async.wait_group %0;" :: "n"(n))

// 1D bulk async copy (TMA path, sm_90 base feature — no 'a' gating)
__device__ __forceinline__ void cp_bulk(uint32_t dst_smem, const void* gsrc,
                                        uint32_t bytes, uint32_t mbar) {
    asm volatile(
        "cp.async.bulk.shared::cluster.global.mbarrier::complete_tx::bytes "
        "[%0], [%1], %2, [%3];"
        :: "r"(dst_smem), "l"(gsrc), "r"(bytes), "r"(mbar) : "memory");
}
#define MBAR_INIT(mb, n) \
    asm volatile("mbarrier.init.shared.b64 [%0], %1;" :: "r"(mb), "r"((uint32_t)(n)) : "memory")
#define MBAR_EXPECT_TX(mb, n) \
    asm volatile("mbarrier.arrive.expect_tx.shared.b64 _, [%0], %1;" \
                 :: "r"(mb), "r"((uint32_t)(n)) : "memory")
#define MBAR_WAIT(mb, ph) do {                                                      \
    uint32_t _mb = (mb), _ph = (ph), _done;                                         \
    asm volatile("{\n\t.reg .pred p;\n\t"                                           \
        "mbarrier.try_wait.parity.acquire.cta.shared::cta.b64 p, [%1], %2;\n\t"     \
        "selp.b32 %0, 1, 0, p;\n\t}" : "=r"(_done) : "r"(_mb), "r"(_ph) : "memory");\
    if (!_done) {                                                                   \
        asm volatile("{\n\t.reg .pred P1;\n\tWL_%=:\n\t"                            \
            "mbarrier.try_wait.parity.acquire.cta.shared::cta.b64 P1, [%0], %1, 0x989680;\n\t" \
            "@P1 bra.uni WD_%=;\n\tbra.uni WL_%=;\n\tWD_%=:\n\t}"                   \
            :: "r"(_mb), "r"(_ph) : "memory");                                      \
    }                                                                               \
} while (0)

__device__ __forceinline__ void split2(float v, __half& hi, __half& lo) {
    hi = __float2half(v);
    lo = __float2half(v - __half2float(hi));
}

// ================= PREP A (token path) =======================================
#define NB_SPLITX 4096
#define NB_WDQKV  1536
#define NB_BIASD  2
#define PA_OFF1 (NB_SPLITX)
#define PA_OFF2 (PA_OFF1 + NB_WDQKV)
#define PA_TOTAL (PA_OFF2 + NB_BIASD)

__global__ __launch_bounds__(256) void prep_a(
    const float* __restrict__ x,
    const float* __restrict__ wdq, const float* __restrict__ wdkv,
    const float* __restrict__ bdq, const float* __restrict__ bdkv,
    __half* __restrict__ xcat, __half* __restrict__ wdqkvc, float* __restrict__ biasd) {
    int bid = blockIdx.x, tid = threadIdx.x;
    if (bid < PA_OFF1) {
        int i4 = bid * 256 + tid;
        int base = i4 * 4;
        int row = base >> 10, col = base & 1023;
        float4 v = *(const float4*)(x + base);
        __half h0, l0, h1, l1, h2, l2, h3, l3;
        split2(v.x, h0, l0); split2(v.y, h1, l1);
        split2(v.z, h2, l2); split2(v.w, h3, l3);
        __half* r = xcat + (size_t)row * 3072 + col;
        *(__half2*)(r + 0) = __halves2half2(h0, h1);
        *(__half2*)(r + 2) = __halves2half2(h2, h3);
        *(__half2*)(r + 1024) = __halves2half2(l0, l1);
        *(__half2*)(r + 1026) = __halves2half2(l2, l3);
        *(__half2*)(r + 2048) = __halves2half2(h0, h1);
        *(__half2*)(r + 2050) = __halves2half2(h2, h3);
    } else if (bid < PA_OFF2) {
        int i = (bid - PA_OFF1) * 256 + tid;
        if (i < 1024 * 384) {
            int k = i / 384, j = i - k * 384;
            float v = (j < 128) ? wdq[k * 128 + j]
                                : (j < 320 ? wdkv[k * 192 + (j - 128)] : 0.f);
            __half hi, lo; split2(v, hi, lo);
            wdqkvc[(size_t)k * 384 + j] = hi;
            wdqkvc[(size_t)(1024 + k) * 384 + j] = hi;
            wdqkvc[(size_t)(2048 + k) * 384 + j] = lo;
        }
    } else {
        int j = (bid - PA_OFF2) * 256 + tid;
        if (j < 384)
            biasd[j] = (j < 128) ? bdq[j] : (j < 320 ? bdkv[j - 128] : 0.f);
    }
}

// ================= PREP B (weight path) ======================================
#define NB_WUQG   32
#define NB_WUQP   256
#define NB_BIASE  6
#define NB_WFA    1024
#define NB_WFB    2048
#define NB_BOEFF  64
#define PB_OFF1 (NB_WUQG)
#define PB_OFF2 (PB_OFF1 + NB_WUQP)
#define PB_OFF3 (PB_OFF2 + NB_BIASE)
#define PB_OFF4 (PB_OFF3 + NB_WFA)
#define PB_OFF5 (PB_OFF4 + NB_WFB)
#define PB_TOTAL (PB_OFF5 + NB_BOEFF)

__global__ __launch_bounds__(256) void prep_b(
    const float* __restrict__ wuq, const float* __restrict__ buq,
    const float* __restrict__ wukuv, const float* __restrict__ bukuv,
    const float* __restrict__ wo,
    __half* __restrict__ wuqeffc, float* __restrict__ biase,
    __half* __restrict__ wfA, __half* __restrict__ wfB, float* __restrict__ bopart) {
    __shared__ float Aq[64][33];
    __shared__ float Bk[64][132];
    int bid = blockIdx.x, tid = threadIdx.x;

    if (bid < PB_OFF1) {
        int h = bid >> 2, r0 = (bid & 3) * 32;
        #pragma unroll
        for (int it = 0; it < 8; it++) {
            int e = it * 256 + tid;
            int r = e >> 6, j = e & 63;
            Aq[j][r] = wuq[(size_t)(r0 + r) * 1024 + h * 96 + j];
        }
        #pragma unroll
        for (int it = 0; it < 32; it++) {
            int e = it * 256 + tid;
            int c = e >> 6, j = e & 63;
            Bk[j][c] = wukuv[(size_t)c * 2560 + h * 64 + j];
        }
        __syncthreads();
        int ty = tid >> 5, tx = tid & 31;
        float acc[4][4];
        #pragma unroll
        for (int i = 0; i < 4; i++)
            #pragma unroll
            for (int k = 0; k < 4; k++) acc[i][k] = 0.f;
        #pragma unroll 8
        for (int j = 0; j < 64; j++) {
            float a[4];
            #pragma unroll
            for (int i = 0; i < 4; i++) a[i] = Aq[j][ty * 4 + i];
            float4 b4 = *(float4*)&Bk[j][tx * 4];
            float bb[4] = {b4.x, b4.y, b4.z, b4.w};
            #pragma unroll
            for (int i = 0; i < 4; i++)
                #pragma unroll
                for (int k = 0; k < 4; k++) acc[i][k] += a[i] * bb[k];
        }
        #pragma unroll
        for (int i = 0; i < 4; i++) {
            #pragma unroll
            for (int k = 0; k < 4; k++) {
                float v = acc[i][k] * SCALE_;
                __half hi, lo; split2(v, hi, lo);
                int r = r0 + ty * 4 + i;
                int col = h * 192 + tx * 4 + k;
                wuqeffc[(size_t)r * 1536 + col] = hi;
                wuqeffc[(size_t)(128 + r) * 1536 + col] = hi;
                wuqeffc[(size_t)(256 + r) * 1536 + col] = lo;
            }
        }
    } else if (bid < PB_OFF2) {
        int i = (bid - PB_OFF1) * 256 + tid;
        if (i < 128 * 512) {
            int r = i >> 9, rem = i & 511;
            int h = rem >> 6, cc = rem & 63;
            float v = (cc < 32) ? wuq[(size_t)r * 1024 + h * 96 + 64 + cc]
                                : wuq[(size_t)r * 1024 + 768 + h * 32 + (cc - 32)];
            v *= SCALE_;
            __half hi, lo; split2(v, hi, lo);
            int col = h * 192 + 128 + cc;
            wuqeffc[(size_t)r * 1536 + col] = hi;
            wuqeffc[(size_t)(128 + r) * 1536 + col] = hi;
            wuqeffc[(size_t)(256 + r) * 1536 + col] = lo;
        }
    } else if (bid < PB_OFF3) {
        int col = (bid - PB_OFF2) * 256 + tid;
        if (col < 1536) {
            int h = col / 192, c = col - h * 192;
            float v;
            if (c < 128) {
                float s = 0.f;
                const float* bq = buq + h * 96;
                const float* wk = wukuv + (size_t)c * 2560 + h * 64;
                #pragma unroll 8
                for (int j = 0; j < 64; j++) s += bq[j] * wk[j];
                v = s;
            } else if (c < 160) {
                v = buq[h * 96 + 64 + (c - 128)];
            } else {
                v = buq[768 + h * 32 + (c - 160)];
            }
            biase[col] = v * SCALE_;
        }
    } else if (bid < PB_OFF4) {
        int i = (bid - PB_OFF3) * 256 + tid;
        if (i < 8 * 128 * 256) {
            int h = i >> 15, rem = i & 32767;
            int c = rem >> 8, v = rem & 255;
            float val = wukuv[(size_t)c * 2560 + 512 + h * 256 + v];
            __half hi, lo; split2(val, hi, lo);
            __half* base = wfA + ((size_t)h * 128 + c) * 768;
            base[v] = hi;
            base[256 + v] = lo;
            base[512 + v] = hi;
        }
    } else if (bid < PB_OFF5) {
        int i4 = (bid - PB_OFF4) * 256 + tid;
        int elem = i4 * 4;
        int h = elem >> 18, rem = elem & 262143;
        int v = rem >> 10, o = rem & 1023;
        float4 val = *(const float4*)(wo + ((size_t)h * 256 + v) * 1024 + o);
        __half h0, l0, h1, l1, h2, l2, h3, l3;
        split2(val.x, h0, l0); split2(val.y, h1, l1);
        split2(val.z, h2, l2); split2(val.w, h3, l3);
        __half* base = wfB + (size_t)h * 768 * 1024;
        __half* p0 = base + (size_t)v * 1024 + o;
        __half* p1 = base + (size_t)(256 + v) * 1024 + o;
        __half* p2 = base + (size_t)(512 + v) * 1024 + o;
        *(__half2*)(p0 + 0) = __halves2half2(h0, h1);
        *(__half2*)(p0 + 2) = __halves2half2(h2, h3);
        *(__half2*)(p1 + 0) = __halves2half2(h0, h1);
        *(__half2*)(p1 + 2) = __halves2half2(h2, h3);
        *(__half2*)(p2 + 0) = __halves2half2(l0, l1);
        *(__half2*)(p2 + 2) = __halves2half2(l2, l3);
    } else {
        int bid2 = bid - PB_OFF5;
        int z = bid2 >> 2;
        int o = (bid2 & 3) * 256 + tid;
        float s = 0.f;
        #pragma unroll 8
        for (int r = z * 128; r < (z + 1) * 128; r++)
            s += bukuv[512 + r] * wo[(size_t)r * 1024 + o];
        bopart[(size_t)z * 1024 + o] = s;
    }
}

__global__ void prep_boeff2(const float* __restrict__ bo, const float* __restrict__ part,
                            float* __restrict__ be) {
    int o = blockIdx.x * 256 + threadIdx.x;
    float s = bo[o];
    #pragma unroll
    for (int z = 0; z < 16; z++) s += part[(size_t)z * 1024 + o];
    be[o] = s;
}

// ---------------- fp16 tensor-core GEMM: 3-stage cp.async pipeline -----------
#define HS_A (128 * 40)
#define HS_B (32 * 136)
#define HS_BYTES ((3 * HS_A + 3 * HS_B) * (int)sizeof(__half))
template <int MODE>
__global__ __launch_bounds__(256, 2) void hgemm(
    const __half* __restrict__ A, const __half* __restrict__ Bm,
    const float* __restrict__ bias, void* __restrict__ Cv, int M, int N, int K,
    int lda, size_t zA, size_t zB, size_t zC, const int* __restrict__ pos) {
    extern __shared__ __half hsm[];

    A += blockIdx.z * zA;
    Bm += blockIdx.z * zB;

    int tid = threadIdx.x, lane = tid & 31, w = tid >> 5;
    int wr = w >> 2, wc = w & 3;
    int row0 = blockIdx.y * 128, col0 = blockIdx.x * 128;

    float acc[16][4];
    #pragma unroll
    for (int i = 0; i < 16; i++)
        #pragma unroll
        for (int j = 0; j < 4; j++) acc[i][j] = 0.f;

    int nk = K >> 5;

    auto load_tile = [&](int st, int k0) {
        const __half* Ab = A + (size_t)row0 * lda + k0;
        __half* Asd = hsm + st * HS_A;
        #pragma unroll
        for (int it = 0; it < 2; it++) {
            int e = it * 256 + tid;
            int r = e >> 2, c = (e & 3) * 8;
            cp16(Asd + r * 40 + c, Ab + (size_t)r * lda + c);
        }
        const __half* Bb = Bm + (size_t)k0 * N + col0;
        __half* Bsd = hsm + 3 * HS_A + st * HS_B;
        #pragma unroll
        for (int it = 0; it < 2; it++) {
            int e = it * 256 + tid;
            int r = e >> 4, c = (e & 15) * 8;
            cp16(Bsd + r * 136 + c, Bb + (size_t)r * N + c);
        }
    };

    load_tile(0, 0);
    CP_COMMIT();
    load_tile(1, 32);
    CP_COMMIT();

    int cur = 0;
    for (int kt = 0; kt < nk; kt++) {
        CP_WAIT(1);
        __syncthreads();
        if (kt + 2 < nk) load_tile((kt + 2) % 3, (kt + 2) << 5);
        CP_COMMIT();

        const __half* Asc = hsm + cur * HS_A;
        const __half* Bsc = hsm + 3 * HS_A + cur * HS_B;
        #pragma unroll
        for (int kk = 0; kk < 2; kk++) {
            uint32_t af[4][4], bf[2][4];
            #pragma unroll
            for (int mt = 0; mt < 4; mt++) {
                int r = wr * 64 + mt * 16 + (lane & 15);
                int c = kk * 16 + ((lane >> 4) << 3);
                ldsm_x4(af[mt], smem_u32(Asc + r * 40 + c));
            }
            #pragma unroll
            for (int nt2 = 0; nt2 < 2; nt2++) {
                int kr = kk * 16 + (lane & 7) + (lane & 8);
                int nc = wc * 32 + nt2 * 16 + ((lane >> 4) << 3);
                ldsm_x4_t(bf[nt2], smem_u32(Bsc + kr * 136 + nc));
            }
            #pragma unroll
            for (int mt = 0; mt < 4; mt++)
                #pragma unroll
                for (int nt = 0; nt < 4; nt++)
                    mma16816(acc[mt * 4 + nt], af[mt], bf[nt >> 1] + (nt & 1) * 2);
        }
        cur = (cur + 1 == 3) ? 0 : cur + 1;
    }

    float bz = (MODE == 0 && blockIdx.z > 0) ? 0.f : 1.f;
    #pragma unroll
    for (int mt = 0; mt < 4; mt++) {
        #pragma unroll
        for (int nt = 0; nt < 4; nt++) {
            int row = row0 + wr * 64 + mt * 16 + (lane >> 2);
            int col = col0 + wc * 32 + nt * 8 + (lane & 3) * 2;
            float b0 = bias[col] * bz, b1 = bias[col + 1] * bz;
            float v0 = acc[mt * 4 + nt][0] + b0;
            float v1 = acc[mt * 4 + nt][1] + b1;
            float v2 = acc[mt * 4 + nt][2] + b0;
            float v3 = acc[mt * 4 + nt][3] + b1;
            if (MODE == 0) {
                float* C = (float*)Cv + blockIdx.z * zC;
                *(float2*)(C + (size_t)row * N + col) = make_float2(v0, v1);
                *(float2*)(C + (size_t)(row + 8) * N + col) = make_float2(v2, v3);
            } else if (MODE == 1) {
                __half* C = (__half*)Cv + blockIdx.z * zC;
                *(__half2*)(C + (size_t)row * N + col) = __floats2half2_rn(v0, v1);
                *(__half2*)(C + (size_t)(row + 8) * N + col) = __floats2half2_rn(v2, v3);
            } else {
                // qe layout: [bh][s][KP], rope on cols c>=160 (pairs in-thread)
                __half* C = (__half*)Cv;
                int h = col / 192, c = col - h * 192;
                if (c >= 160) {
                    int i2 = (c - 160) >> 1;
                    float freq = powf(10000.f, -(float)(2 * i2) / 32.f);
                    float p0f = (float)pos[row], p1f = (float)pos[row + 8];
                    float a0 = p0f * freq, a1 = p1f * freq;
                    float c0 = cosf(a0), s0 = sinf(a0);
                    float c1 = cosf(a1), s1 = sinf(a1);
                    float t0 = v0 * c0 - v1 * s0, t1 = v0 * s0 + v1 * c0;
                    v0 = t0; v1 = t1;
                    t0 = v2 * c1 - v3 * s1; t1 = v2 * s1 + v3 * c1;
                    v2 = t0; v3 = t1;
                }
                int b = row >> 11, s = row & 2047;
                *(__half2*)(C + (((size_t)(b * 8 + h)) * S_ + s) * KP + c) =
                    __floats2half2_rn(v0, v1);
                int row2 = row + 8;
                b = row2 >> 11; s = row2 & 2047;
                *(__half2*)(C + (((size_t)(b * 8 + h)) * S_ + s) * KP + c) =
                    __floats2half2_rn(v2, v3);
            }
        }
    }
}

// ---------------- fused post-dqkv: sum split-K + 2x rmsnorm + k-rope ---------
__global__ void postproc(const float* __restrict__ dqkvA, const float* __restrict__ dqkvB,
                         const int* __restrict__ pos,
                         const float* __restrict__ qnw, const float* __restrict__ kvnw,
                         __half* __restrict__ cqcat, __half* __restrict__ keff) {
    __shared__ float r1[128], r2[128];
    int t = blockIdx.x, d = threadIdx.x;
    const float* rowA = dqkvA + (size_t)t * 384;
    const float* rowB = dqkvB + (size_t)t * 384;
    float qv = rowA[d] + rowB[d];
    float kvv = rowA[128 + d] + rowB[128 + d];
    r1[d] = qv * qv;
    r2[d] = kvv * kvv;
    __syncthreads();
    #pragma unroll
    for (int s = 64; s > 0; s >>= 1) {
        if (d < s) { r1[d] += r1[d + s]; r2[d] += r2[d + s]; }
        __syncthreads();
    }
    float invq = rsqrtf(r1[0] * (1.f / 128.f) + 1e-8f);
    float invk = rsqrtf(r2[0] * (1.f / 128.f) + 1e-8f);
    float cq = qnw[d] * qv * invq;
    __half hi, lo; split2(cq, hi, lo);
    __half* cr = cqcat + (size_t)t * 384;
    cr[d] = hi;
    cr[128 + d] = lo;
    cr[256 + d] = hi;
    keff[(size_t)t * KP + d] = __float2half(kvnw[d] * kvv * invk);
    if (d < 32) {
        float p = (float)pos[t];
        float freq = powf(10000.f, -(float)(2 * d) / 64.f);
        float ang = p * freq;
        float c = cosf(ang), s = sinf(ang);
        float xe = rowA[256 + 2 * d] + rowB[256 + 2 * d];
        float xo = rowA[256 + 2 * d + 1] + rowB[256 + 2 * d + 1];
        keff[(size_t)t * KP + 128 + 2 * d]     = __float2half(xe * c - xo * s);
        keff[(size_t)t * KP + 128 + 2 * d + 1] = __float2half(xe * s + xo * c);
    }
}

// ---------------- absorbed flash attention (bulk-copy K/Q loads) --------------
// smem: 2 stages x 64 x KP halves (51200 B) + 2 mbarriers (16 B).
#define KTILE_B (64 * KP * 2)        // 25600
#define FL_BYTES (2 * 64 * KP * 2 + 16)
__global__ __launch_bounds__(256, 1) void flash_mla(
    const __half* __restrict__ Qe, const __half* __restrict__ Ke,
    __half* __restrict__ Out) {
    extern __shared__ __half sm[];
    uint32_t smb = smem_u32(sm);
    uint32_t mb0 = smb + 2 * 64 * KP * 2;
    uint32_t mb1 = mb0 + 8;

    int tid = threadIdx.x, lane = tid & 31, w = tid >> 5;
    int bh = blockIdx.y;
    int b = bh >> 3, h = bh & 7;
    int q0 = blockIdx.x * 128;

    if (tid == 0) {
        MBAR_INIT(mb0, 1);
        MBAR_INIT(mb1, 1);
    }
    __syncthreads();

    // Q: 128 rows x KP halves = 51200 B, one bulk into both stages
    if (tid == 0) {
        MBAR_EXPECT_TX(mb0, 2 * KTILE_B);
        cp_bulk(smb, Qe + ((size_t)bh * S_ + q0) * KP, 2 * KTILE_B, mb0);
    }
    MBAR_WAIT(mb0, 0);

    uint32_t qf[12][4];
    #pragma unroll
    for (int ks = 0; ks < 12; ks++) {
        int r = w * 16 + (lane & 15);
        int c = ks * 16 + ((lane >> 4) << 3);
        ldsm_x4(qf[ks], smem_u32(&sm[r * KP + c]));
    }
    __syncthreads();   // everyone pulled Q before K overwrites

    const __half* kbase = Ke + (size_t)b * S_ * KP;

    // prologue: tiles 0 (stage0/mb0) and 1 (stage1/mb1)
    if (tid == 0) {
        MBAR_EXPECT_TX(mb0, KTILE_B);
        cp_bulk(smb, kbase, KTILE_B, mb0);
        MBAR_EXPECT_TX(mb1, KTILE_B);
        cp_bulk(smb + KTILE_B, kbase + (size_t)64 * KP, KTILE_B, mb1);
    }
    int ph0 = 1, ph1 = 0;   // mb0 already consumed phase 0 by Q

    float m[2] = {-1e30f, -1e30f}, l[2] = {0.f, 0.f};
    float o[16][4];
    #pragma unroll
    for (int i = 0; i < 16; i++)
        #pragma unroll
        for (int j = 0; j < 4; j++) o[i][j] = 0.f;

    for (int kb = 0; kb < S_ / 64; kb++) {
        int st = kb & 1;
        if (st == 0) { MBAR_WAIT(mb0, ph0); ph0 ^= 1; }
        else         { MBAR_WAIT(mb1, ph1); ph1 ^= 1; }
        const __half* Ks = sm + st * 64 * KP;

        float s[8][4];
        #pragma unroll
        for (int i = 0; i < 8; i++)
            #pragma unroll
            for (int j = 0; j < 4; j++) s[i][j] = 0.f;
        #pragma unroll
        for (int ks = 0; ks < 12; ks++) {
            #pragma unroll
            for (int nt2 = 0; nt2 < 4; nt2++) {
                uint32_t bfr[4];
                int n = nt2 * 16 + ((lane >> 4) << 3) + (lane & 7);
                int k = ks * 16 + (lane & 8);
                ldsm_x4(bfr, smem_u32(&Ks[n * KP + k]));
                mma16816(s[2 * nt2],     qf[ks], bfr + 0);
                mma16816(s[2 * nt2 + 1], qf[ks], bfr + 2);
            }
        }

        #pragma unroll
        for (int rr = 0; rr < 2; rr++) {
            float mx = -1e30f;
            #pragma unroll
            for (int j = 0; j < 8; j++)
                mx = fmaxf(mx, fmaxf(s[j][2 * rr], s[j][2 * rr + 1]));
            mx = fmaxf(mx, __shfl_xor_sync(0xffffffffu, mx, 1));
            mx = fmaxf(mx, __shfl_xor_sync(0xffffffffu, mx, 2));
            float m_new = fmaxf(m[rr], mx);
            float alpha = __expf(m[rr] - m_new);
            float tsum = 0.f;
            #pragma unroll
            for (int j = 0; j < 8; j++) {
                float p0 = __expf(s[j][2 * rr] - m_new);
                float p1 = __expf(s[j][2 * rr + 1] - m_new);
                s[j][2 * rr] = p0;
                s[j][2 * rr + 1] = p1;
                tsum += p0 + p1;
            }
            tsum += __shfl_xor_sync(0xffffffffu, tsum, 1);
            tsum += __shfl_xor_sync(0xffffffffu, tsum, 2);
            l[rr] = l[rr] * alpha + tsum;
            m[rr] = m_new;
            #pragma unroll
            for (int j = 0; j < 16; j++) {
                o[j][2 * rr] *= alpha;
                o[j][2 * rr + 1] *= alpha;
            }
        }

        uint32_t pf[4][4];
        #pragma unroll
        for (int kk = 0; kk < 4; kk++) {
            pf[kk][0] = pack_h2(s[2 * kk][0],     s[2 * kk][1]);
            pf[kk][1] = pack_h2(s[2 * kk][2],     s[2 * kk][3]);
            pf[kk][2] = pack_h2(s[2 * kk + 1][0], s[2 * kk + 1][1]);
            pf[kk][3] = pack_h2(s[2 * kk + 1][2], s[2 * kk + 1][3]);
        }

        #pragma unroll
        for (int kk = 0; kk < 4; kk++) {
            #pragma unroll
            for (int nt2 = 0; nt2 < 8; nt2++) {
                uint32_t bfr[4];
                int k = kk * 16 + (lane & 7) + (lane & 8);
                int n = nt2 * 16 + ((lane >> 4) << 3);
                ldsm_x4_t(bfr, smem_u32(&Ks[k * KP + n]));
                mma16816(o[2 * nt2],     pf[kk], bfr + 0);
                mma16816(o[2 * nt2 + 1], pf[kk], bfr + 2);
            }
        }
        __syncthreads();   // stage free
        if (kb + 2 < S_ / 64 && tid == 0) {
            uint32_t mb = st ? mb1 : mb0;
            MBAR_EXPECT_TX(mb, KTILE_B);
            cp_bulk(smb + st * KTILE_B, kbase + (size_t)(kb + 2) * 64 * KP,
                    KTILE_B, mb);
        }
    }

    #pragma unroll
    for (int rr = 0; rr < 2; rr++) {
        float inv = 1.f / l[rr];
        int row = q0 + w * 16 + (lane >> 2) + rr * 8;
        size_t base = ((size_t)(b * S_) + row) * 1024 + h * 128;
        #pragma unroll
        for (int j = 0; j < 16; j++) {
            int c = j * 8 + (lane & 3) * 2;
            *(__half2*)&Out[base + c] =
                __floats2half2_rn(o[j][2 * rr] * inv, o[j][2 * rr + 1] * inv);
        }
    }
}

// ---------------- launch -----------------------------------------------------
extern "C" void kernel_launch(void* const* d_in, const int* in_sizes, int n_in,
                              void* d_out, int out_size) {
    const float* x        = (const float*)d_in[0];
    const int*   pos      = (const int*)d_in[1];
    const float* w_dq_w   = (const float*)d_in[2];
    const float* w_dq_b   = (const float*)d_in[3];
    const float* q_norm_w = (const float*)d_in[4];
    const float* w_uq_w   = (const float*)d_in[5];
    const float* w_uq_b   = (const float*)d_in[6];
    const float* w_dkv_w  = (const float*)d_in[7];
    const float* w_dkv_b  = (const float*)d_in[8];
    const float* kv_norm_w= (const float*)d_in[9];
    const float* w_ukuv_w = (const float*)d_in[10];
    const float* w_ukuv_b = (const float*)d_in[11];
    const float* w_o_w    = (const float*)d_in[12];
    const float* w_o_b    = (const float*)d_in[13];
    float* out = (float*)d_out;

    __half *xcat, *wdqkv, *cqcat, *wuqeff, *qe, *keff, *attnlat, *wfA, *wfB, *wfused;
    float *dqkv, *bias_dqkv, *biaseff, *bopart, *boeff, *zb;
    cudaGetSymbolAddress((void**)&xcat,     g_xcat);
    cudaGetSymbolAddress((void**)&wdqkv,    g_wdqkv);
    cudaGetSymbolAddress((void**)&bias_dqkv,g_bias_dqkv);
    cudaGetSymbolAddress((void**)&dqkv,     g_dqkv);
    cudaGetSymbolAddress((void**)&cqcat,    g_cqcat);
    cudaGetSymbolAddress((void**)&wuqeff,   g_wuqeff);
    cudaGetSymbolAddress((void**)&biaseff,  g_biaseff);
    cudaGetSymbolAddress((void**)&qe,       g_qe);
    cudaGetSymbolAddress((void**)&keff,     g_keff);
    cudaGetSymbolAddress((void**)&attnlat,  g_attnlat);
    cudaGetSymbolAddress((void**)&wfA,      g_wfA);
    cudaGetSymbolAddress((void**)&wfB,      g_wfB);
    cudaGetSymbolAddress((void**)&wfused,   g_wfused);
    cudaGetSymbolAddress((void**)&bopart,   g_bopart);
    cudaGetSymbolAddress((void**)&boeff,    g_boeff);
    cudaGetSymbolAddress((void**)&zb,       g_zb);

    static cudaStream_t s2 = nullptr;
    static cudaEvent_t eFork = nullptr, eJ1 = nullptr, eJ2 = nullptr;
    static bool attr_done = false;
    if (!s2) {
        cudaStreamCreateWithFlags(&s2, cudaStreamNonBlocking);
        cudaEventCreateWithFlags(&eFork, cudaEventDisableTiming);
        cudaEventCreateWithFlags(&eJ1, cudaEventDisableTiming);
        cudaEventCreateWithFlags(&eJ2, cudaEventDisableTiming);
    }
    if (!attr_done) {
        cudaFuncSetAttribute(hgemm<0>, cudaFuncAttributeMaxDynamicSharedMemorySize, HS_BYTES);
        cudaFuncSetAttribute(hgemm<1>, cudaFuncAttributeMaxDynamicSharedMemorySize, HS_BYTES);
        cudaFuncSetAttribute(hgemm<2>, cudaFuncAttributeMaxDynamicSharedMemorySize, HS_BYTES);
        cudaFuncSetAttribute(flash_mla, cudaFuncAttributeMaxDynamicSharedMemorySize, FL_BYTES);
        attr_done = true;
    }

    // ---- fork: branch B (weight prep + wfused) on s2 ----
    cudaEventRecord(eFork, 0);
    cudaStreamWaitEvent(s2, eFork, 0);

    prep_b<<<PB_TOTAL, 256, 0, s2>>>(w_uq_w, w_uq_b, w_ukuv_w, w_ukuv_b, w_o_w,
                                     wuqeff, biaseff, wfA, wfB, bopart);
    cudaEventRecord(eJ1, s2);
    prep_boeff2<<<4, 256, 0, s2>>>(w_o_b, bopart, boeff);
    hgemm<1><<<dim3(8, 1, 8), 256, HS_BYTES, s2>>>(
        wfA, wfB, zb, wfused, 128, 1024, 768, 768,
        (size_t)128 * 768, (size_t)768 * 1024, (size_t)128 * 1024, nullptr);
    cudaEventRecord(eJ2, s2);

    // ---- branch A (token path) ----
    prep_a<<<PA_TOTAL, 256>>>(x, w_dq_w, w_dkv_w, w_dq_b, w_dkv_b,
                              xcat, wdqkv, bias_dqkv);
    hgemm<0><<<dim3(3, 32, 2), 256, HS_BYTES>>>(
        xcat, wdqkv, bias_dqkv, dqkv, T_, 384, 1536, 3072,
        (size_t)1536, (size_t)1536 * 384, (size_t)T_ * 384, nullptr);
    postproc<<<T_, 128>>>(dqkv, dqkv + (size_t)T_ * 384, pos, q_norm_w, kv_norm_w,
                          cqcat, keff);

    cudaStreamWaitEvent(0, eJ1, 0);
    hgemm<2><<<dim3(12, 32, 1), 256, HS_BYTES>>>(
        cqcat, wuqeff, biaseff, qe, T_, 1536, 384, 384, 0, 0, 0, pos);

    flash_mla<<<dim3(S_ / 128, 16), 256, FL_BYTES>>>(qe, keff, attnlat);

    cudaStreamWaitEvent(0, eJ2, 0);
    hgemm<0><<<dim3(8, 32, 1), 256, HS_BYTES>>>(
        attnlat, wfused, boeff, out, T_, 1024, 1024, 1024, 0, 0, 0, nullptr);
}

// round 16
// speedup vs baseline: 1.4414x; 1.4414x over previous
#include <cuda_runtime.h>
#include <cuda_fp16.h>
#include <math.h>
#include <stdint.h>

#define B_   2
#define S_   2048
#define T_   4096      // B*S tokens
#define DIM_ 1024
#define SCALE_ 0.08838834764831845f   // 1/sqrt(128)
#define KP   200       // smem pitch for flash tiles (gmem stays pitch 192)

// ---------------- scratch (static device arrays) -----------------------------
__device__ __half g_xcat[T_ * 3072];       // [x_hi | x_lo | x_hi]
__device__ __half g_wdqkv[3072 * 384];     // stacked [Wdq|Wdkv] hi/hi/lo
__device__ float  g_bias_dqkv[384];
__device__ float  g_dqkv[2 * T_ * 384];    // split-K partials (contiguous)
__device__ __half g_cqcat[T_ * 384];       // [cq_hi | cq_lo | cq_hi]
__device__ __half g_wuqeff[384 * 1536];    // absorbed uq weights hi/hi/lo (scaled)
__device__ float  g_biaseff[1536];
__device__ __half g_qe[16 * S_ * 192];     // q_eff [bh][s][192] fp16
__device__ __half g_keff[T_ * 192];        // [ckv_norm(128) | roped krope(64)]
__device__ __half g_attnlat[T_ * 1024];    // attn latent [t][h*128+c] fp16
__device__ __half g_wfA[8 * 128 * 768];
__device__ __half g_wfB[8 * 768 * 1024];
__device__ __half g_wfused[1024 * 1024];
__device__ float  g_bopart[16 * 1024];
__device__ float  g_boeff[1024];
__device__ float  g_zb[1536];

// ---------------- helpers ------------------------------------------------------
__device__ __forceinline__ uint32_t smem_u32(const void* p) {
    return (uint32_t)__cvta_generic_to_shared(p);
}
__device__ __forceinline__ void ldsm_x4(uint32_t* r, uint32_t addr) {
    asm volatile("ldmatrix.sync.aligned.m8n8.x4.shared.b16 {%0,%1,%2,%3},[%4];"
                 : "=r"(r[0]), "=r"(r[1]), "=r"(r[2]), "=r"(r[3]) : "r"(addr));
}
__device__ __forceinline__ void ldsm_x4_t(uint32_t* r, uint32_t addr) {
    asm volatile("ldmatrix.sync.aligned.m8n8.x4.trans.shared.b16 {%0,%1,%2,%3},[%4];"
                 : "=r"(r[0]), "=r"(r[1]), "=r"(r[2]), "=r"(r[3]) : "r"(addr));
}
__device__ __forceinline__ void mma16816(float* c, const uint32_t* a, const uint32_t* b) {
    asm volatile(
        "mma.sync.aligned.m16n8k16.row.col.f32.f16.f16.f32 "
        "{%0,%1,%2,%3},{%4,%5,%6,%7},{%8,%9},{%0,%1,%2,%3};"
        : "+f"(c[0]), "+f"(c[1]), "+f"(c[2]), "+f"(c[3])
        : "r"(a[0]), "r"(a[1]), "r"(a[2]), "r"(a[3]), "r"(b[0]), "r"(b[1]));
}
__device__ __forceinline__ uint32_t pack_h2(float lo, float hi) {
    __half2 h = __floats2half2_rn(lo, hi);
    return *(uint32_t*)&h;
}
__device__ __forceinline__ void cp16(void* smem_dst, const void* gsrc) {
    asm volatile("cp.async.cg.shared.global [%0],[%1],16;"
                 :: "r"(smem_u32(smem_dst)), "l"(gsrc));
}
#define CP_COMMIT() asm volatile("cp.async.commit_group;")
#define CP_WAIT(n)  asm volatile("cp.async.wait_group %0;" :: "n"(n))

__device__ __forceinline__ void split2(float v, __half& hi, __half& lo) {
    hi = __float2half(v);
    lo = __float2half(v - __half2float(hi));
}

// ================= PREP A (token path) =======================================
#define NB_SPLITX 4096
#define NB_WDQKV  1536
#define NB_BIASD  2
#define PA_OFF1 (NB_SPLITX)
#define PA_OFF2 (PA_OFF1 + NB_WDQKV)
#define PA_TOTAL (PA_OFF2 + NB_BIASD)

__global__ __launch_bounds__(256) void prep_a(
    const float* __restrict__ x,
    const float* __restrict__ wdq, const float* __restrict__ wdkv,
    const float* __restrict__ bdq, const float* __restrict__ bdkv,
    __half* __restrict__ xcat, __half* __restrict__ wdqkvc, float* __restrict__ biasd) {
    int bid = blockIdx.x, tid = threadIdx.x;
    if (bid < PA_OFF1) {
        int i4 = bid * 256 + tid;
        int base = i4 * 4;
        int row = base >> 10, col = base & 1023;
        float4 v = *(const float4*)(x + base);
        __half h0, l0, h1, l1, h2, l2, h3, l3;
        split2(v.x, h0, l0); split2(v.y, h1, l1);
        split2(v.z, h2, l2); split2(v.w, h3, l3);
        __half* r = xcat + (size_t)row * 3072 + col;
        *(__half2*)(r + 0) = __halves2half2(h0, h1);
        *(__half2*)(r + 2) = __halves2half2(h2, h3);
        *(__half2*)(r + 1024) = __halves2half2(l0, l1);
        *(__half2*)(r + 1026) = __halves2half2(l2, l3);
        *(__half2*)(r + 2048) = __halves2half2(h0, h1);
        *(__half2*)(r + 2050) = __halves2half2(h2, h3);
    } else if (bid < PA_OFF2) {
        int i = (bid - PA_OFF1) * 256 + tid;
        if (i < 1024 * 384) {
            int k = i / 384, j = i - k * 384;
            float v = (j < 128) ? wdq[k * 128 + j]
                                : (j < 320 ? wdkv[k * 192 + (j - 128)] : 0.f);
            __half hi, lo; split2(v, hi, lo);
            wdqkvc[(size_t)k * 384 + j] = hi;
            wdqkvc[(size_t)(1024 + k) * 384 + j] = hi;
            wdqkvc[(size_t)(2048 + k) * 384 + j] = lo;
        }
    } else {
        int j = (bid - PA_OFF2) * 256 + tid;
        if (j < 384)
            biasd[j] = (j < 128) ? bdq[j] : (j < 320 ? bdkv[j - 128] : 0.f);
    }
}

// ================= PREP B (weight path) ======================================
#define NB_WUQG   32
#define NB_WUQP   256
#define NB_BIASE  6
#define NB_WFA    1024
#define NB_WFB    2048
#define NB_BOEFF  64
#define PB_OFF1 (NB_WUQG)
#define PB_OFF2 (PB_OFF1 + NB_WUQP)
#define PB_OFF3 (PB_OFF2 + NB_BIASE)
#define PB_OFF4 (PB_OFF3 + NB_WFA)
#define PB_OFF5 (PB_OFF4 + NB_WFB)
#define PB_TOTAL (PB_OFF5 + NB_BOEFF)

__global__ __launch_bounds__(256) void prep_b(
    const float* __restrict__ wuq, const float* __restrict__ buq,
    const float* __restrict__ wukuv, const float* __restrict__ bukuv,
    const float* __restrict__ wo,
    __half* __restrict__ wuqeffc, float* __restrict__ biase,
    __half* __restrict__ wfA, __half* __restrict__ wfB, float* __restrict__ bopart) {
    __shared__ float Aq[64][33];
    __shared__ float Bk[64][132];
    int bid = blockIdx.x, tid = threadIdx.x;

    if (bid < PB_OFF1) {
        int h = bid >> 2, r0 = (bid & 3) * 32;
        #pragma unroll
        for (int it = 0; it < 8; it++) {
            int e = it * 256 + tid;
            int r = e >> 6, j = e & 63;
            Aq[j][r] = wuq[(size_t)(r0 + r) * 1024 + h * 96 + j];
        }
        #pragma unroll
        for (int it = 0; it < 32; it++) {
            int e = it * 256 + tid;
            int c = e >> 6, j = e & 63;
            Bk[j][c] = wukuv[(size_t)c * 2560 + h * 64 + j];
        }
        __syncthreads();
        int ty = tid >> 5, tx = tid & 31;
        float acc[4][4];
        #pragma unroll
        for (int i = 0; i < 4; i++)
            #pragma unroll
            for (int k = 0; k < 4; k++) acc[i][k] = 0.f;
        #pragma unroll 8
        for (int j = 0; j < 64; j++) {
            float a[4];
            #pragma unroll
            for (int i = 0; i < 4; i++) a[i] = Aq[j][ty * 4 + i];
            float4 b4 = *(float4*)&Bk[j][tx * 4];
            float bb[4] = {b4.x, b4.y, b4.z, b4.w};
            #pragma unroll
            for (int i = 0; i < 4; i++)
                #pragma unroll
                for (int k = 0; k < 4; k++) acc[i][k] += a[i] * bb[k];
        }
        #pragma unroll
        for (int i = 0; i < 4; i++) {
            #pragma unroll
            for (int k = 0; k < 4; k++) {
                float v = acc[i][k] * SCALE_;
                __half hi, lo; split2(v, hi, lo);
                int r = r0 + ty * 4 + i;
                int col = h * 192 + tx * 4 + k;
                wuqeffc[(size_t)r * 1536 + col] = hi;
                wuqeffc[(size_t)(128 + r) * 1536 + col] = hi;
                wuqeffc[(size_t)(256 + r) * 1536 + col] = lo;
            }
        }
    } else if (bid < PB_OFF2) {
        int i = (bid - PB_OFF1) * 256 + tid;
        if (i < 128 * 512) {
            int r = i >> 9, rem = i & 511;
            int h = rem >> 6, cc = rem & 63;
            float v = (cc < 32) ? wuq[(size_t)r * 1024 + h * 96 + 64 + cc]
                                : wuq[(size_t)r * 1024 + 768 + h * 32 + (cc - 32)];
            v *= SCALE_;
            __half hi, lo; split2(v, hi, lo);
            int col = h * 192 + 128 + cc;
            wuqeffc[(size_t)r * 1536 + col] = hi;
            wuqeffc[(size_t)(128 + r) * 1536 + col] = hi;
            wuqeffc[(size_t)(256 + r) * 1536 + col] = lo;
        }
    } else if (bid < PB_OFF3) {
        int col = (bid - PB_OFF2) * 256 + tid;
        if (col < 1536) {
            int h = col / 192, c = col - h * 192;
            float v;
            if (c < 128) {
                float s = 0.f;
                const float* bq = buq + h * 96;
                const float* wk = wukuv + (size_t)c * 2560 + h * 64;
                #pragma unroll 8
                for (int j = 0; j < 64; j++) s += bq[j] * wk[j];
                v = s;
            } else if (c < 160) {
                v = buq[h * 96 + 64 + (c - 128)];
            } else {
                v = buq[768 + h * 32 + (c - 160)];
            }
            biase[col] = v * SCALE_;
        }
    } else if (bid < PB_OFF4) {
        int i = (bid - PB_OFF3) * 256 + tid;
        if (i < 8 * 128 * 256) {
            int h = i >> 15, rem = i & 32767;
            int c = rem >> 8, v = rem & 255;
            float val = wukuv[(size_t)c * 2560 + 512 + h * 256 + v];
            __half hi, lo; split2(val, hi, lo);
            __half* base = wfA + ((size_t)h * 128 + c) * 768;
            base[v] = hi;
            base[256 + v] = lo;
            base[512 + v] = hi;
        }
    } else if (bid < PB_OFF5) {
        int i4 = (bid - PB_OFF4) * 256 + tid;
        int elem = i4 * 4;
        int h = elem >> 18, rem = elem & 262143;
        int v = rem >> 10, o = rem & 1023;
        float4 val = *(const float4*)(wo + ((size_t)h * 256 + v) * 1024 + o);
        __half h0, l0, h1, l1, h2, l2, h3, l3;
        split2(val.x, h0, l0); split2(val.y, h1, l1);
        split2(val.z, h2, l2); split2(val.w, h3, l3);
        __half* base = wfB + (size_t)h * 768 * 1024;
        __half* p0 = base + (size_t)v * 1024 + o;
        __half* p1 = base + (size_t)(256 + v) * 1024 + o;
        __half* p2 = base + (size_t)(512 + v) * 1024 + o;
        *(__half2*)(p0 + 0) = __halves2half2(h0, h1);
        *(__half2*)(p0 + 2) = __halves2half2(h2, h3);
        *(__half2*)(p1 + 0) = __halves2half2(h0, h1);
        *(__half2*)(p1 + 2) = __halves2half2(h2, h3);
        *(__half2*)(p2 + 0) = __halves2half2(l0, l1);
        *(__half2*)(p2 + 2) = __halves2half2(l2, l3);
    } else {
        int bid2 = bid - PB_OFF5;
        int z = bid2 >> 2;
        int o = (bid2 & 3) * 256 + tid;
        float s = 0.f;
        #pragma unroll 8
        for (int r = z * 128; r < (z + 1) * 128; r++)
            s += bukuv[512 + r] * wo[(size_t)r * 1024 + o];
        bopart[(size_t)z * 1024 + o] = s;
    }
}

__global__ void prep_boeff2(const float* __restrict__ bo, const float* __restrict__ part,
                            float* __restrict__ be) {
    int o = blockIdx.x * 256 + threadIdx.x;
    float s = bo[o];
    #pragma unroll
    for (int z = 0; z < 16; z++) s += part[(size_t)z * 1024 + o];
    be[o] = s;
}

// ---------------- fp16 tensor-core GEMM: 3-stage cp.async pipeline -----------
#define HS_A (128 * 40)
#define HS_B (32 * 136)
#define HS_BYTES ((3 * HS_A + 3 * HS_B) * (int)sizeof(__half))
template <int MODE>
__global__ __launch_bounds__(256, 2) void hgemm(
    const __half* __restrict__ A, const __half* __restrict__ Bm,
    const float* __restrict__ bias, void* __restrict__ Cv, int M, int N, int K,
    int lda, size_t zA, size_t zB, size_t zC, const int* __restrict__ pos) {
    extern __shared__ __half hsm[];

    A += blockIdx.z * zA;
    Bm += blockIdx.z * zB;

    int tid = threadIdx.x, lane = tid & 31, w = tid >> 5;
    int wr = w >> 2, wc = w & 3;
    int row0 = blockIdx.y * 128, col0 = blockIdx.x * 128;

    float acc[16][4];
    #pragma unroll
    for (int i = 0; i < 16; i++)
        #pragma unroll
        for (int j = 0; j < 4; j++) acc[i][j] = 0.f;

    int nk = K >> 5;

    auto load_tile = [&](int st, int k0) {
        const __half* Ab = A + (size_t)row0 * lda + k0;
        __half* Asd = hsm + st * HS_A;
        #pragma unroll
        for (int it = 0; it < 2; it++) {
            int e = it * 256 + tid;
            int r = e >> 2, c = (e & 3) * 8;
            cp16(Asd + r * 40 + c, Ab + (size_t)r * lda + c);
        }
        const __half* Bb = Bm + (size_t)k0 * N + col0;
        __half* Bsd = hsm + 3 * HS_A + st * HS_B;
        #pragma unroll
        for (int it = 0; it < 2; it++) {
            int e = it * 256 + tid;
            int r = e >> 4, c = (e & 15) * 8;
            cp16(Bsd + r * 136 + c, Bb + (size_t)r * N + c);
        }
    };

    load_tile(0, 0);
    CP_COMMIT();
    load_tile(1, 32);
    CP_COMMIT();

    int cur = 0;
    for (int kt = 0; kt < nk; kt++) {
        CP_WAIT(1);
        __syncthreads();
        if (kt + 2 < nk) load_tile((kt + 2) % 3, (kt + 2) << 5);
        CP_COMMIT();

        const __half* Asc = hsm + cur * HS_A;
        const __half* Bsc = hsm + 3 * HS_A + cur * HS_B;
        #pragma unroll
        for (int kk = 0; kk < 2; kk++) {
            uint32_t af[4][4], bf[2][4];
            #pragma unroll
            for (int mt = 0; mt < 4; mt++) {
                int r = wr * 64 + mt * 16 + (lane & 15);
                int c = kk * 16 + ((lane >> 4) << 3);
                ldsm_x4(af[mt], smem_u32(Asc + r * 40 + c));
            }
            #pragma unroll
            for (int nt2 = 0; nt2 < 2; nt2++) {
                int kr = kk * 16 + (lane & 7) + (lane & 8);
                int nc = wc * 32 + nt2 * 16 + ((lane >> 4) << 3);
                ldsm_x4_t(bf[nt2], smem_u32(Bsc + kr * 136 + nc));
            }
            #pragma unroll
            for (int mt = 0; mt < 4; mt++)
                #pragma unroll
                for (int nt = 0; nt < 4; nt++)
                    mma16816(acc[mt * 4 + nt], af[mt], bf[nt >> 1] + (nt & 1) * 2);
        }
        cur = (cur + 1 == 3) ? 0 : cur + 1;
    }

    float bz = (MODE == 0 && blockIdx.z > 0) ? 0.f : 1.f;
    #pragma unroll
    for (int mt = 0; mt < 4; mt++) {
        #pragma unroll
        for (int nt = 0; nt < 4; nt++) {
            int row = row0 + wr * 64 + mt * 16 + (lane >> 2);
            int col = col0 + wc * 32 + nt * 8 + (lane & 3) * 2;
            float b0 = bias[col] * bz, b1 = bias[col + 1] * bz;
            float v0 = acc[mt * 4 + nt][0] + b0;
            float v1 = acc[mt * 4 + nt][1] + b1;
            float v2 = acc[mt * 4 + nt][2] + b0;
            float v3 = acc[mt * 4 + nt][3] + b1;
            if (MODE == 0) {
                float* C = (float*)Cv + blockIdx.z * zC;
                *(float2*)(C + (size_t)row * N + col) = make_float2(v0, v1);
                *(float2*)(C + (size_t)(row + 8) * N + col) = make_float2(v2, v3);
            } else if (MODE == 1) {
                __half* C = (__half*)Cv + blockIdx.z * zC;
                *(__half2*)(C + (size_t)row * N + col) = __floats2half2_rn(v0, v1);
                *(__half2*)(C + (size_t)(row + 8) * N + col) = __floats2half2_rn(v2, v3);
            } else {
                // qe layout: [bh][s][192], rope on cols c>=160 (pairs in-thread)
                __half* C = (__half*)Cv;
                int h = col / 192, c = col - h * 192;
                if (c >= 160) {
                    int i2 = (c - 160) >> 1;
                    float freq = powf(10000.f, -(float)(2 * i2) / 32.f);
                    float p0f = (float)pos[row], p1f = (float)pos[row + 8];
                    float a0 = p0f * freq, a1 = p1f * freq;
                    float c0 = cosf(a0), s0 = sinf(a0);
                    float c1 = cosf(a1), s1 = sinf(a1);
                    float t0 = v0 * c0 - v1 * s0, t1 = v0 * s0 + v1 * c0;
                    v0 = t0; v1 = t1;
                    t0 = v2 * c1 - v3 * s1; t1 = v2 * s1 + v3 * c1;
                    v2 = t0; v3 = t1;
                }
                int b = row >> 11, s = row & 2047;
                *(__half2*)(C + (((size_t)(b * 8 + h)) * S_ + s) * 192 + c) =
                    __floats2half2_rn(v0, v1);
                int row2 = row + 8;
                b = row2 >> 11; s = row2 & 2047;
                *(__half2*)(C + (((size_t)(b * 8 + h)) * S_ + s) * 192 + c) =
                    __floats2half2_rn(v2, v3);
            }
        }
    }
}

// ---------------- fused post-dqkv: sum split-K + 2x rmsnorm + k-rope ---------
__global__ void postproc(const float* __restrict__ dqkvA, const float* __restrict__ dqkvB,
                         const int* __restrict__ pos,
                         const float* __restrict__ qnw, const float* __restrict__ kvnw,
                         __half* __restrict__ cqcat, __half* __restrict__ keff) {
    __shared__ float r1[128], r2[128];
    int t = blockIdx.x, d = threadIdx.x;
    const float* rowA = dqkvA + (size_t)t * 384;
    const float* rowB = dqkvB + (size_t)t * 384;
    float qv = rowA[d] + rowB[d];
    float kvv = rowA[128 + d] + rowB[128 + d];
    r1[d] = qv * qv;
    r2[d] = kvv * kvv;
    __syncthreads();
    #pragma unroll
    for (int s = 64; s > 0; s >>= 1) {
        if (d < s) { r1[d] += r1[d + s]; r2[d] += r2[d + s]; }
        __syncthreads();
    }
    float invq = rsqrtf(r1[0] * (1.f / 128.f) + 1e-8f);
    float invk = rsqrtf(r2[0] * (1.f / 128.f) + 1e-8f);
    float cq = qnw[d] * qv * invq;
    __half hi, lo; split2(cq, hi, lo);
    __half* cr = cqcat + (size_t)t * 384;
    cr[d] = hi;
    cr[128 + d] = lo;
    cr[256 + d] = hi;
    keff[(size_t)t * 192 + d] = __float2half(kvnw[d] * kvv * invk);
    if (d < 32) {
        float p = (float)pos[t];
        float freq = powf(10000.f, -(float)(2 * d) / 64.f);
        float ang = p * freq;
        float c = cosf(ang), s = sinf(ang);
        float xe = rowA[256 + 2 * d] + rowB[256 + 2 * d];
        float xo = rowA[256 + 2 * d + 1] + rowB[256 + 2 * d + 1];
        keff[(size_t)t * 192 + 128 + 2 * d]     = __float2half(xe * c - xo * s);
        keff[(size_t)t * 192 + 128 + 2 * d + 1] = __float2half(xe * s + xo * c);
    }
}

// ---------------- absorbed flash attention (Q in smem, 2 CTAs/SM) ------------
// smem: K stages 2 x 64 x KP + Q 128 x KP = 256*KP halves = 102400 B.
#define FL_BYTES (256 * KP * (int)sizeof(__half))
__global__ __launch_bounds__(256, 2) void flash_mla(
    const __half* __restrict__ Qe, const __half* __restrict__ Ke,
    __half* __restrict__ Out) {
    extern __shared__ __half sm[];
    __half* Qs = sm + 2 * 64 * KP;

    int tid = threadIdx.x, lane = tid & 31, w = tid >> 5;
    int bh = blockIdx.y;
    int b = bh >> 3, h = bh & 7;
    int q0 = blockIdx.x * 128;

    // load Q tile 128 x 192 into persistent smem region (pitch KP)
    {
        const __half* qbase = Qe + ((size_t)bh * S_ + q0) * 192;
        #pragma unroll
        for (int it = 0; it < 12; it++) {
            int e = it * 256 + tid;
            int r = e / 24, c = (e % 24) * 8;
            cp16(&Qs[r * KP + c], qbase + (size_t)r * 192 + c);
        }
    }
    CP_COMMIT();

    const __half* kbase = Ke + (size_t)b * S_ * 192;
    // prologue: K tiles 0 and 1
    #pragma unroll
    for (int it = 0; it < 6; it++) {
        int e = it * 256 + tid;
        int r = e / 24, c = (e % 24) * 8;
        cp16(&sm[r * KP + c], kbase + (size_t)r * 192 + c);
    }
    CP_COMMIT();
    #pragma unroll
    for (int it = 0; it < 6; it++) {
        int e = it * 256 + tid;
        int r = e / 24, c = (e % 24) * 8;
        cp16(&sm[64 * KP + r * KP + c], kbase + (size_t)(64 + r) * 192 + c);
    }
    CP_COMMIT();

    float m[2] = {-1e30f, -1e30f}, l[2] = {0.f, 0.f};
    float o[16][4];
    #pragma unroll
    for (int i = 0; i < 16; i++)
        #pragma unroll
        for (int j = 0; j < 4; j++) o[i][j] = 0.f;

    int qrow = w * 16 + (lane & 15);
    int qcol8 = (lane >> 4) << 3;

    for (int kb = 0; kb < S_ / 64; kb++) {
        CP_WAIT(1);        // Q + tiles up to kb landed
        __syncthreads();

        const __half* Ks = sm + (kb & 1) * 64 * KP;

        // S = Qe @ Ke^T (Q frags reloaded from smem per k-step: 4 regs each)
        float s[8][4];
        #pragma unroll
        for (int i = 0; i < 8; i++)
            #pragma unroll
            for (int j = 0; j < 4; j++) s[i][j] = 0.f;
        #pragma unroll
        for (int ks = 0; ks < 12; ks++) {
            uint32_t qf[4];
            ldsm_x4(qf, smem_u32(&Qs[qrow * KP + ks * 16 + qcol8]));
            #pragma unroll
            for (int nt2 = 0; nt2 < 4; nt2++) {
                uint32_t bfr[4];
                int n = nt2 * 16 + ((lane >> 4) << 3) + (lane & 7);
                int k = ks * 16 + (lane & 8);
                ldsm_x4(bfr, smem_u32(&Ks[n * KP + k]));
                mma16816(s[2 * nt2],     qf, bfr + 0);
                mma16816(s[2 * nt2 + 1], qf, bfr + 2);
            }
        }

        // online softmax (rows lane>>2 and +8)
        #pragma unroll
        for (int rr = 0; rr < 2; rr++) {
            float mx = -1e30f;
            #pragma unroll
            for (int j = 0; j < 8; j++)
                mx = fmaxf(mx, fmaxf(s[j][2 * rr], s[j][2 * rr + 1]));
            mx = fmaxf(mx, __shfl_xor_sync(0xffffffffu, mx, 1));
            mx = fmaxf(mx, __shfl_xor_sync(0xffffffffu, mx, 2));
            float m_new = fmaxf(m[rr], mx);
            float alpha = __expf(m[rr] - m_new);
            float tsum = 0.f;
            #pragma unroll
            for (int j = 0; j < 8; j++) {
                float p0 = __expf(s[j][2 * rr] - m_new);
                float p1 = __expf(s[j][2 * rr + 1] - m_new);
                s[j][2 * rr] = p0;
                s[j][2 * rr + 1] = p1;
                tsum += p0 + p1;
            }
            tsum += __shfl_xor_sync(0xffffffffu, tsum, 1);
            tsum += __shfl_xor_sync(0xffffffffu, tsum, 2);
            l[rr] = l[rr] * alpha + tsum;
            m[rr] = m_new;
            #pragma unroll
            for (int j = 0; j < 16; j++) {
                o[j][2 * rr] *= alpha;
                o[j][2 * rr + 1] *= alpha;
            }
        }

        uint32_t pf[4][4];
        #pragma unroll
        for (int kk = 0; kk < 4; kk++) {
            pf[kk][0] = pack_h2(s[2 * kk][0],     s[2 * kk][1]);
            pf[kk][1] = pack_h2(s[2 * kk][2],     s[2 * kk][3]);
            pf[kk][2] = pack_h2(s[2 * kk + 1][0], s[2 * kk + 1][1]);
            pf[kk][3] = pack_h2(s[2 * kk + 1][2], s[2 * kk + 1][3]);
        }

        // O += P @ V, V = Ks[:, 0:128]
        #pragma unroll
        for (int kk = 0; kk < 4; kk++) {
            #pragma unroll
            for (int nt2 = 0; nt2 < 8; nt2++) {
                uint32_t bfr[4];
                int k = kk * 16 + (lane & 7) + (lane & 8);
                int n = nt2 * 16 + ((lane >> 4) << 3);
                ldsm_x4_t(bfr, smem_u32(&Ks[k * KP + n]));
                mma16816(o[2 * nt2],     pf[kk], bfr + 0);
                mma16816(o[2 * nt2 + 1], pf[kk], bfr + 2);
            }
        }
        __syncthreads();   // stage consumed by all warps
        if (kb + 2 < S_ / 64) {
            const __half* kb2 = kbase + (size_t)(kb + 2) * 64 * 192;
            __half* Kd = sm + (kb & 1) * 64 * KP;
            #pragma unroll
            for (int it = 0; it < 6; it++) {
                int e = it * 256 + tid;
                int r = e / 24, c = (e % 24) * 8;
                cp16(&Kd[r * KP + c], kb2 + (size_t)r * 192 + c);
            }
        }
        CP_COMMIT();
    }

    #pragma unroll
    for (int rr = 0; rr < 2; rr++) {
        float inv = 1.f / l[rr];
        int row = q0 + w * 16 + (lane >> 2) + rr * 8;
        size_t base = ((size_t)(b * S_) + row) * 1024 + h * 128;
        #pragma unroll
        for (int j = 0; j < 16; j++) {
            int c = j * 8 + (lane & 3) * 2;
            *(__half2*)&Out[base + c] =
                __floats2half2_rn(o[j][2 * rr] * inv, o[j][2 * rr + 1] * inv);
        }
    }
}

// ---------------- launch -----------------------------------------------------
extern "C" void kernel_launch(void* const* d_in, const int* in_sizes, int n_in,
                              void* d_out, int out_size) {
    const float* x        = (const float*)d_in[0];
    const int*   pos      = (const int*)d_in[1];
    const float* w_dq_w   = (const float*)d_in[2];
    const float* w_dq_b   = (const float*)d_in[3];
    const float* q_norm_w = (const float*)d_in[4];
    const float* w_uq_w   = (const float*)d_in[5];
    const float* w_uq_b   = (const float*)d_in[6];
    const float* w_dkv_w  = (const float*)d_in[7];
    const float* w_dkv_b  = (const float*)d_in[8];
    const float* kv_norm_w= (const float*)d_in[9];
    const float* w_ukuv_w = (const float*)d_in[10];
    const float* w_ukuv_b = (const float*)d_in[11];
    const float* w_o_w    = (const float*)d_in[12];
    const float* w_o_b    = (const float*)d_in[13];
    float* out = (float*)d_out;

    __half *xcat, *wdqkv, *cqcat, *wuqeff, *qe, *keff, *attnlat, *wfA, *wfB, *wfused;
    float *dqkv, *bias_dqkv, *biaseff, *bopart, *boeff, *zb;
    cudaGetSymbolAddress((void**)&xcat,     g_xcat);
    cudaGetSymbolAddress((void**)&wdqkv,    g_wdqkv);
    cudaGetSymbolAddress((void**)&bias_dqkv,g_bias_dqkv);
    cudaGetSymbolAddress((void**)&dqkv,     g_dqkv);
    cudaGetSymbolAddress((void**)&cqcat,    g_cqcat);
    cudaGetSymbolAddress((void**)&wuqeff,   g_wuqeff);
    cudaGetSymbolAddress((void**)&biaseff,  g_biaseff);
    cudaGetSymbolAddress((void**)&qe,       g_qe);
    cudaGetSymbolAddress((void**)&keff,     g_keff);
    cudaGetSymbolAddress((void**)&attnlat,  g_attnlat);
    cudaGetSymbolAddress((void**)&wfA,      g_wfA);
    cudaGetSymbolAddress((void**)&wfB,      g_wfB);
    cudaGetSymbolAddress((void**)&wfused,   g_wfused);
    cudaGetSymbolAddress((void**)&bopart,   g_bopart);
    cudaGetSymbolAddress((void**)&boeff,    g_boeff);
    cudaGetSymbolAddress((void**)&zb,       g_zb);

    static cudaStream_t s2 = nullptr;
    static cudaEvent_t eFork = nullptr, eJ1 = nullptr, eJ2 = nullptr;
    static bool attr_done = false;
    if (!s2) {
        cudaStreamCreateWithFlags(&s2, cudaStreamNonBlocking);
        cudaEventCreateWithFlags(&eFork, cudaEventDisableTiming);
        cudaEventCreateWithFlags(&eJ1, cudaEventDisableTiming);
        cudaEventCreateWithFlags(&eJ2, cudaEventDisableTiming);
    }
    if (!attr_done) {
        cudaFuncSetAttribute(hgemm<0>, cudaFuncAttributeMaxDynamicSharedMemorySize, HS_BYTES);
        cudaFuncSetAttribute(hgemm<1>, cudaFuncAttributeMaxDynamicSharedMemorySize, HS_BYTES);
        cudaFuncSetAttribute(hgemm<2>, cudaFuncAttributeMaxDynamicSharedMemorySize, HS_BYTES);
        cudaFuncSetAttribute(flash_mla, cudaFuncAttributeMaxDynamicSharedMemorySize, FL_BYTES);
        attr_done = true;
    }

    // ---- fork: branch B (weight prep + wfused) on s2 ----
    cudaEventRecord(eFork, 0);
    cudaStreamWaitEvent(s2, eFork, 0);

    prep_b<<<PB_TOTAL, 256, 0, s2>>>(w_uq_w, w_uq_b, w_ukuv_w, w_ukuv_b, w_o_w,
                                     wuqeff, biaseff, wfA, wfB, bopart);
    cudaEventRecord(eJ1, s2);
    prep_boeff2<<<4, 256, 0, s2>>>(w_o_b, bopart, boeff);
    hgemm<1><<<dim3(8, 1, 8), 256, HS_BYTES, s2>>>(
        wfA, wfB, zb, wfused, 128, 1024, 768, 768,
        (size_t)128 * 768, (size_t)768 * 1024, (size_t)128 * 1024, nullptr);
    cudaEventRecord(eJ2, s2);

    // ---- branch A (token path) ----
    prep_a<<<PA_TOTAL, 256>>>(x, w_dq_w, w_dkv_w, w_dq_b, w_dkv_b,
                              xcat, wdqkv, bias_dqkv);
    hgemm<0><<<dim3(3, 32, 2), 256, HS_BYTES>>>(
        xcat, wdqkv, bias_dqkv, dqkv, T_, 384, 1536, 3072,
        (size_t)1536, (size_t)1536 * 384, (size_t)T_ * 384, nullptr);
    postproc<<<T_, 128>>>(dqkv, dqkv + (size_t)T_ * 384, pos, q_norm_w, kv_norm_w,
                          cqcat, keff);

    cudaStreamWaitEvent(0, eJ1, 0);
    hgemm<2><<<dim3(12, 32, 1), 256, HS_BYTES>>>(
        cqcat, wuqeff, biaseff, qe, T_, 1536, 384, 384, 0, 0, 0, pos);

    flash_mla<<<dim3(S_ / 128, 16), 256, FL_BYTES>>>(qe, keff, attnlat);

    cudaStreamWaitEvent(0, eJ2, 0);
    hgemm<0><<<dim3(8, 32, 1), 256, HS_BYTES>>>(
        attnlat, wfused, boeff, out, T_, 1024, 1024, 1024, 0, 0, 0, nullptr);
}